// round 11
// baseline (speedup 1.0000x reference)
#include <cuda_runtime.h>
#include <cstdint>

// Problem dims
#define DM     1792           // D_MODEL
#define BBDIM  256            // BB
#define I_DIM  2048           // inner dim I
#define G_DIM  8192           // 4*I
#define ROWB   8192           // bytes per K=2048 row
#define ROWBF  7168           // bytes per K=1792 row
#define SMEM_DYN 32768        // 4 rows x 8KB stage (fits default 48KB limit)

// Scratch state (allocation-free rule: __device__ globals)
__device__ float g_z[6 * G_DIM];      // gate preactivations (Wih part + biases)
__device__ float g_h[2][I_DIM];       // ping-pong hidden state
__device__ float g_c[2][I_DIM];       // ping-pong cell state

__device__ __forceinline__ float sigmoidf_(float x) {
    return 1.0f / (1.0f + expf(-x));
}
__device__ __forceinline__ float dot4(float4 a, float4 b) {
    return a.x * b.x + a.y * b.y + a.z * b.z + a.w * b.w;
}
__device__ __forceinline__ float warp_sum(float v) {
#pragma unroll
    for (int o = 16; o > 0; o >>= 1) v += __shfl_xor_sync(0xffffffffu, v, o);
    return v;
}

// ---------------- TMA bulk-copy plumbing ----------------
__device__ __forceinline__ uint32_t smem_u32(const void* p) {
    return (uint32_t)__cvta_generic_to_shared(p);
}
__device__ __forceinline__ void mbar_init(uint32_t m, uint32_t cnt) {
    asm volatile("mbarrier.init.shared.b64 [%0], %1;" :: "r"(m), "r"(cnt) : "memory");
    asm volatile("fence.proxy.async.shared::cta;" ::: "memory");
}
__device__ __forceinline__ void mbar_expect(uint32_t m, uint32_t tx) {
    asm volatile("mbarrier.arrive.expect_tx.shared.b64 _, [%0], %1;"
                 :: "r"(m), "r"(tx) : "memory");
}
__device__ __forceinline__ void bulk_g2s(uint32_t dst, const void* src,
                                         uint32_t bytes, uint32_t mbar) {
    asm volatile(
        "cp.async.bulk.shared::cluster.global.mbarrier::complete_tx::bytes "
        "[%0], [%1], %2, [%3];"
        :: "r"(dst), "l"(src), "r"(bytes), "r"(mbar) : "memory");
}
__device__ __forceinline__ void mbar_wait(uint32_t m, uint32_t parity) {
    asm volatile(
        "{\n\t.reg .pred P;\n"
        "WL_%=:\n\t"
        "mbarrier.try_wait.parity.shared.b64 P, [%0], %1, 0x989680;\n\t"
        "@P bra DONE_%=;\n\t"
        "bra WL_%=;\n"
        "DONE_%=:\n\t}"
        :: "r"(m), "r"(parity) : "memory");
}

// One smem row vs smem vector, NIT float4 per lane.
template <int NIT>
__device__ __forceinline__ float row_dot_smem(const char* stage_row,
                                              const float* vsm, int lane)
{
    const float4* r = (const float4*)stage_row;
    const float4* v = (const float4*)vsm;
    float a0 = 0.f, a1 = 0.f;
#pragma unroll
    for (int i = 0; i < NIT; i += 2) {
        a0 += dot4(r[lane + i * 32],       v[lane + i * 32]);
        a1 += dot4(r[lane + (i + 1) * 32], v[lane + (i + 1) * 32]);
    }
    return a0 + a1;
}

// ---------------------------------------------------------------------------
// K0: z for cells 0,1. Block = 4 consecutive rows of Wih5[t] (one 32KB bulk);
// warp w reduces row r0+w. Grid: 2 * 2048 blocks.
// ---------------------------------------------------------------------------
__global__ void __launch_bounds__(128) k0_bulk(
    const float* __restrict__ x, const float* __restrict__ y,
    const float* __restrict__ Wih5,
    const float* __restrict__ bih5, const float* __restrict__ bhh5)
{
    extern __shared__ char stage[];
    __shared__ float vsm[I_DIM];
    __shared__ __align__(8) unsigned long long mbar;

    const int tid = threadIdx.x, w = tid >> 5, lane = tid & 31;
    const int t  = blockIdx.x >> 11;               // cell 0 or 1
    const int r0 = (blockIdx.x & 2047) << 2;       // first of 4 rows
    const uint32_t mb = smem_u32(&mbar);

    if (tid == 0) mbar_init(mb, 1);
    __syncthreads();
    if (tid == 0) {
        mbar_expect(mb, 4 * ROWB);
        bulk_g2s(smem_u32(stage),
                 Wih5 + ((size_t)t * G_DIM + r0) * I_DIM, 4 * ROWB, mb);
    }
    for (int k = tid; k < DM; k += 128)    vsm[k]      = x[t * DM + k];
    for (int k = tid; k < BBDIM; k += 128) vsm[DM + k] = y[t * BBDIM + k];
    __syncthreads();
    mbar_wait(mb, 0);

    float s = warp_sum(row_dot_smem<16>(stage + (size_t)w * ROWB, vsm, lane));
    if (lane == 0) {
        const size_t zb = (size_t)t * G_DIM + r0 + w;
        g_z[zb] = s + bih5[zb] + bhh5[zb];
    }
}

// ---------------------------------------------------------------------------
// step 0: h0 = c0 = 0 -> no Whh read.
// ---------------------------------------------------------------------------
__global__ void step0_kernel() {
    int j = blockIdx.x * blockDim.x + threadIdx.x;
    if (j >= I_DIM) return;
    float zi = g_z[j];
    float zg = g_z[2 * I_DIM + j];
    float zo = g_z[3 * I_DIM + j];
    float c  = sigmoidf_(zi) * tanhf(zg);
    float h  = sigmoidf_(zo) * tanhf(c);
    g_c[0][j] = c;
    g_h[0][j] = h;
}

// ---------------------------------------------------------------------------
// Fused step. Blocks [0,2048): rec — block owns ONE j; 4 bulk copies of 8KB
// (gate rows g*2048+j); warp w reduces gate w; thread 0 does the epilogue.
// Blocks >= 2048: z for the next cell.
//   mode 0: 4 consecutive rows of Wih5[t+1] (2048 z-blocks, K=2048)
//   mode 1: final-cell slice of WihF (256 z-blocks, K=1792)
// ---------------------------------------------------------------------------
__global__ void __launch_bounds__(128) fused_bulk(
    const float* __restrict__ whh, int zoff, int pin, int pout,
    const float* __restrict__ wz,
    const float* __restrict__ xvec, const float* __restrict__ yvec,
    const float* __restrict__ bih,  const float* __restrict__ bhh,
    int zout, int mode)
{
    extern __shared__ char stage[];
    __shared__ float vsm[I_DIM];
    __shared__ float dots[4];
    __shared__ __align__(8) unsigned long long mbar;

    const int tid = threadIdx.x, w = tid >> 5, lane = tid & 31;
    const uint32_t mb = smem_u32(&mbar);

    if (tid == 0) mbar_init(mb, 1);
    __syncthreads();

    if (blockIdx.x < 2048) {
        const int j = blockIdx.x;
        if (tid == 0) {
            mbar_expect(mb, 4 * ROWB);
#pragma unroll
            for (int g = 0; g < 4; ++g)
                bulk_g2s(smem_u32(stage) + g * ROWB,
                         whh + ((size_t)g * I_DIM + j) * I_DIM, ROWB, mb);
        }
        {
            const float4* gh4 = (const float4*)g_h[pin];
            float4* s4 = (float4*)vsm;
#pragma unroll
            for (int k = 0; k < 4; ++k) s4[tid + k * 128] = gh4[tid + k * 128];
        }
        __syncthreads();
        mbar_wait(mb, 0);

        float s = warp_sum(row_dot_smem<16>(stage + (size_t)w * ROWB, vsm, lane));
        if (lane == 0) dots[w] = s;
        __syncthreads();

        if (tid == 0) {
            const float* z = g_z + zoff;
            float gi = z[j]             + dots[0];
            float gf = z[I_DIM + j]     + dots[1];
            float gg = z[2 * I_DIM + j] + dots[2];
            float go = z[3 * I_DIM + j] + dots[3];
            float c  = sigmoidf_(gf) * g_c[pin][j] + sigmoidf_(gi) * tanhf(gg);
            float h  = sigmoidf_(go) * tanhf(c);
            g_c[pout][j] = c;
            g_h[pout][j] = h;
        }
    } else {
        const int q = blockIdx.x - 2048;
        if (mode == 0) {
            const int r0 = q << 2;
            if (tid == 0) {
                mbar_expect(mb, 4 * ROWB);
                bulk_g2s(smem_u32(stage), wz + (size_t)r0 * I_DIM, 4 * ROWB, mb);
            }
            for (int k = tid; k < DM; k += 128)    vsm[k]      = xvec[k];
            for (int k = tid; k < BBDIM; k += 128) vsm[DM + k] = yvec[k];
            __syncthreads();
            mbar_wait(mb, 0);

            float s = warp_sum(row_dot_smem<16>(stage + (size_t)w * ROWB, vsm, lane));
            if (lane == 0) {
                const int r = r0 + w;
                g_z[zout + r] = s + bih[r] + bhh[r];
            }
        } else {
            const int rl0 = q << 2;                // 0..1020
            const int g   = rl0 >> 8;
            const int jj  = rl0 & 255;
            const int r0  = g * I_DIM + DM + jj;   // 4 consecutive real rows
            if (tid == 0) {
                mbar_expect(mb, 4 * ROWBF);
                bulk_g2s(smem_u32(stage), wz + (size_t)r0 * DM, 4 * ROWBF, mb);
            }
            for (int k = tid; k < DM; k += 128) vsm[k] = xvec[k];
            __syncthreads();
            mbar_wait(mb, 0);

            float s = warp_sum(row_dot_smem<14>(stage + (size_t)w * ROWBF, vsm, lane));
            if (lane == 0) {
                const int r = r0 + w;
                g_z[zout + r] = s + bih[r] + bhh[r];
            }
        }
    }
}

// ---------------------------------------------------------------------------
// Final step: j in [1792,2048). 256 blocks, 1 j each; 4 gate rows of WhhF.
// Writes d_out directly.
// ---------------------------------------------------------------------------
__global__ void __launch_bounds__(128) final_bulk(
    const float* __restrict__ whhF, int pin, float* __restrict__ out)
{
    extern __shared__ char stage[];
    __shared__ float vsm[I_DIM];
    __shared__ float dots[4];
    __shared__ __align__(8) unsigned long long mbar;

    const int tid = threadIdx.x, w = tid >> 5, lane = tid & 31;
    const uint32_t mb = smem_u32(&mbar);

    if (tid == 0) mbar_init(mb, 1);
    __syncthreads();

    const int j = DM + blockIdx.x;
    if (tid == 0) {
        mbar_expect(mb, 4 * ROWB);
#pragma unroll
        for (int g = 0; g < 4; ++g)
            bulk_g2s(smem_u32(stage) + g * ROWB,
                     whhF + ((size_t)g * I_DIM + j) * I_DIM, ROWB, mb);
    }
    {
        const float4* gh4 = (const float4*)g_h[pin];
        float4* s4 = (float4*)vsm;
#pragma unroll
        for (int k = 0; k < 4; ++k) s4[tid + k * 128] = gh4[tid + k * 128];
    }
    __syncthreads();
    mbar_wait(mb, 0);

    float s = warp_sum(row_dot_smem<16>(stage + (size_t)w * ROWB, vsm, lane));
    if (lane == 0) dots[w] = s;
    __syncthreads();

    if (tid == 0) {
        const float* z = g_z + 5 * G_DIM;
        float gi = z[j]             + dots[0];
        float gf = z[I_DIM + j]     + dots[1];
        float gg = z[2 * I_DIM + j] + dots[2];
        float go = z[3 * I_DIM + j] + dots[3];
        float c  = sigmoidf_(gf) * g_c[pin][j] + sigmoidf_(gi) * tanhf(gg);
        float h  = sigmoidf_(go) * tanhf(c);
        out[j - DM] = h;
    }
}

// ---------------------------------------------------------------------------
extern "C" void kernel_launch(void* const* d_in, const int* in_sizes, int n_in,
                              void* d_out, int out_size)
{
    const float* x    = (const float*)d_in[0];
    const float* y    = (const float*)d_in[1];
    const float* Wih5 = (const float*)d_in[2];
    const float* Whh5 = (const float*)d_in[3];
    const float* bih5 = (const float*)d_in[4];
    const float* bhh5 = (const float*)d_in[5];
    const float* WihF = (const float*)d_in[6];
    const float* WhhF = (const float*)d_in[7];
    const float* bihF = (const float*)d_in[8];
    const float* bhhF = (const float*)d_in[9];
    float* out = (float*)d_out;

    (void)in_sizes; (void)n_in; (void)out_size;

    const size_t WSTEP = (size_t)G_DIM * I_DIM;

    // K0: z[0], z[1] (134 MB)
    k0_bulk<<<4096, 128, SMEM_DYN>>>(x, y, Wih5, bih5, bhh5);

    // step 0 (h0=c0=0: skips Whh5[0], 67 MB)
    step0_kernel<<<(I_DIM + 255) / 256, 256>>>();

    // S1..S3: rec t + z(t+1) (134 MB each)
    int pin = 0;
    for (int t = 1; t <= 3; ++t) {
        fused_bulk<<<2048 + 2048, 128, SMEM_DYN>>>(
            Whh5 + (size_t)t * WSTEP, t * G_DIM, pin, 1 - pin,
            Wih5 + (size_t)(t + 1) * WSTEP,
            x + (t + 1) * DM, y + (t + 1) * BBDIM,
            bih5 + (size_t)(t + 1) * G_DIM, bhh5 + (size_t)(t + 1) * G_DIM,
            (t + 1) * G_DIM, /*mode=*/0);
        pin = 1 - pin;
    }

    // S4: rec 4 + final-cell z slice (67 + 7.3 MB)
    fused_bulk<<<2048 + 256, 128, SMEM_DYN>>>(
        Whh5 + (size_t)4 * WSTEP, 4 * G_DIM, pin, 1 - pin,
        WihF, x + 5 * DM, nullptr,
        bihF, bhhF, 5 * G_DIM, /*mode=*/1);
    pin = 1 - pin;

    // S5: final step, 256 outputs (8.4 MB)
    final_bulk<<<256, 128, SMEM_DYN>>>(WhhF, pin, out);
}

// round 13
// speedup vs baseline: 1.2416x; 1.2416x over previous
#include <cuda_runtime.h>
#include <cstdint>

// Problem dims
#define DM     1792           // D_MODEL
#define BBDIM  256            // BB
#define I_DIM  2048           // inner dim I
#define G_DIM  8192           // 4*I

#define HALF   370            // blocks per role
#define NBF    740            // one wave at 5 blocks/SM x 148 SMs

// Chunking: group = 4 rows; each group streamed as 2 chunk-stages (half-K).
#define CH2048B 4096u         // chunk bytes, K=2048 (1024 floats)
#define CH1792B 3584u         // chunk bytes, K=1792 (896 floats)

// Scratch state (allocation-free rule: __device__ globals)
__device__ float g_z[6 * G_DIM];
__device__ float g_h[2][I_DIM];
__device__ float g_c[2][I_DIM];

__device__ __forceinline__ float sigmoidf_(float x) {
    return 1.0f / (1.0f + expf(-x));
}
__device__ __forceinline__ float dot4(float4 a, float4 b) {
    return a.x * b.x + a.y * b.y + a.z * b.z + a.w * b.w;
}
__device__ __forceinline__ float warp_sum(float v) {
#pragma unroll
    for (int o = 16; o > 0; o >>= 1) v += __shfl_xor_sync(0xffffffffu, v, o);
    return v;
}

// ---------------- TMA bulk-copy plumbing ----------------
__device__ __forceinline__ uint32_t smem_u32(const void* p) {
    return (uint32_t)__cvta_generic_to_shared(p);
}
__device__ __forceinline__ void mbar_init(uint32_t m, uint32_t cnt) {
    asm volatile("mbarrier.init.shared.b64 [%0], %1;" :: "r"(m), "r"(cnt) : "memory");
}
__device__ __forceinline__ void fence_async() {
    asm volatile("fence.proxy.async.shared::cta;" ::: "memory");
}
__device__ __forceinline__ void mbar_expect(uint32_t m, uint32_t tx) {
    asm volatile("mbarrier.arrive.expect_tx.shared.b64 _, [%0], %1;"
                 :: "r"(m), "r"(tx) : "memory");
}
__device__ __forceinline__ void bulk_g2s(uint32_t dst, const void* src,
                                         uint32_t bytes, uint32_t mbar) {
    asm volatile(
        "cp.async.bulk.shared::cluster.global.mbarrier::complete_tx::bytes "
        "[%0], [%1], %2, [%3];"
        :: "r"(dst), "l"(src), "r"(bytes), "r"(mbar) : "memory");
}
__device__ __forceinline__ void mbar_wait(uint32_t m, uint32_t parity) {
    asm volatile(
        "{\n\t.reg .pred P;\n"
        "WL_%=:\n\t"
        "mbarrier.try_wait.parity.shared.b64 P, [%0], %1, 0x989680;\n\t"
        "@P bra DONE_%=;\n\t"
        "bra WL_%=;\n"
        "DONE_%=:\n\t}"
        :: "r"(m), "r"(parity) : "memory");
}

// Issue one chunk-stage: 4 rows, rowStrideF floats between rows, chunkB bytes.
__device__ __forceinline__ void issue4(uint32_t dst, const float* base,
                                       size_t rowStrideF, uint32_t chunkB,
                                       uint32_t mb) {
    mbar_expect(mb, 4 * chunkB);
#pragma unroll
    for (int rr = 0; rr < 4; ++rr)
        bulk_g2s(dst + rr * chunkB, base + (size_t)rr * rowStrideF, chunkB, mb);
}

// NIT float4 per lane, conflict-free.
template <int NIT>
__device__ __forceinline__ float chunk_dot(const float4* __restrict__ row,
                                           const float4* __restrict__ v,
                                           int lane) {
    float a = 0.f;
#pragma unroll
    for (int i = 0; i < NIT; ++i) a += dot4(row[lane + i * 32], v[lane + i * 32]);
    return a;
}

// ---------------------------------------------------------------------------
// K0: z for cells 0,1. 740 blocks: bid/370 -> cell. Block loops groups
// s = n0 + 370*g over 2048 groups (group = 4 consecutive rows).
// ---------------------------------------------------------------------------
__global__ void __launch_bounds__(128) k0_pipe(
    const float* __restrict__ x, const float* __restrict__ y,
    const float* __restrict__ Wih5,
    const float* __restrict__ bih5, const float* __restrict__ bhh5)
{
    __shared__ float4 stage[2][1024];       // 2 x 16KB
    __shared__ float  vsm[I_DIM];
    __shared__ __align__(8) unsigned long long mbar[2];

    const int tid = threadIdx.x, w = tid >> 5, lane = tid & 31;
    const uint32_t mb0 = smem_u32(&mbar[0]), mb1 = smem_u32(&mbar[1]);

    if (tid == 0) { mbar_init(mb0, 1); mbar_init(mb1, 1); fence_async(); }
    __syncthreads();

    const int t  = blockIdx.x / HALF;
    const int n0 = blockIdx.x % HALF;
    const float* W = Wih5 + (size_t)t * G_DIM * I_DIM;
    const int ng = (2048 - n0 + HALF - 1) / HALF;

    if (tid == 0) {
        const float* b0 = W + (size_t)(n0 * 4) * I_DIM;
        issue4(smem_u32(stage[0]), b0,        I_DIM, CH2048B, mb0);
        issue4(smem_u32(stage[1]), b0 + 1024, I_DIM, CH2048B, mb1);
    }
    for (int k = tid; k < DM; k += 128)    vsm[k]      = x[t * DM + k];
    for (int k = tid; k < BBDIM; k += 128) vsm[DM + k] = y[t * BBDIM + k];
    __syncthreads();

    for (int g = 0; g < ng; ++g) {
        const int r0 = (n0 + HALF * g) * 4;
        const float* nb = W + (size_t)((n0 + HALF * (g + 1)) * 4) * I_DIM;

        mbar_wait(mb0, g & 1);
        float acc = chunk_dot<8>(stage[0] + w * 256, (const float4*)vsm, lane);
        __syncthreads();
        if (tid == 0 && g + 1 < ng) {
            fence_async();
            issue4(smem_u32(stage[0]), nb, I_DIM, CH2048B, mb0);
        }

        mbar_wait(mb1, g & 1);
        acc += chunk_dot<8>(stage[1] + w * 256, (const float4*)vsm + 256, lane);
        acc = warp_sum(acc);
        if (lane == 0) {
            const size_t zi = (size_t)t * G_DIM + r0 + w;
            g_z[zi] = acc + bih5[zi] + bhh5[zi];
        }
        __syncthreads();
        if (tid == 0 && g + 1 < ng) {
            fence_async();
            issue4(smem_u32(stage[1]), nb + 1024, I_DIM, CH2048B, mb1);
        }
    }
}

// ---------------------------------------------------------------------------
// step 0: h0 = c0 = 0 -> no Whh read.
// ---------------------------------------------------------------------------
__global__ void step0_kernel() {
    int j = blockIdx.x * blockDim.x + threadIdx.x;
    if (j >= I_DIM) return;
    float zi = g_z[j];
    float zg = g_z[2 * I_DIM + j];
    float zo = g_z[3 * I_DIM + j];
    float c  = sigmoidf_(zi) * tanhf(zg);
    float h  = sigmoidf_(zo) * tanhf(c);
    g_c[0][j] = c;
    g_h[0][j] = h;
}

// ---------------------------------------------------------------------------
// Fused step, 740 blocks. [0,370): rec — block loops j = n0 + 370*g over
// 2048 j's (group = 4 gate rows of j, row stride = 2048*2048).
// [370,740): z for next cell. mode 0: 2048 groups of 4 consecutive rows of
// Wih5[t+1], K=2048. mode 1: 256 groups, final-cell slice of WihF, K=1792.
// ---------------------------------------------------------------------------
__global__ void __launch_bounds__(128) fused_pipe(
    const float* __restrict__ whh, int zoff, int pin, int pout,
    const float* __restrict__ wz,
    const float* __restrict__ xvec, const float* __restrict__ yvec,
    const float* __restrict__ bih,  const float* __restrict__ bhh,
    int zout, int mode)
{
    __shared__ float4 stage[2][1024];
    __shared__ float  vsm[I_DIM];
    __shared__ float  dots[4];
    __shared__ __align__(8) unsigned long long mbar[2];

    const int tid = threadIdx.x, w = tid >> 5, lane = tid & 31;
    const uint32_t mb0 = smem_u32(&mbar[0]), mb1 = smem_u32(&mbar[1]);

    if (tid == 0) { mbar_init(mb0, 1); mbar_init(mb1, 1); fence_async(); }
    __syncthreads();

    if (blockIdx.x < HALF) {
        // ---------------- rec role ----------------
        const int n0 = blockIdx.x;
        const int ng = (2048 - n0 + HALF - 1) / HALF;
        const size_t GSTR = (size_t)I_DIM * I_DIM;   // gate-row stride

        if (tid == 0) {
            const float* b0 = whh + (size_t)n0 * I_DIM;
            issue4(smem_u32(stage[0]), b0,        GSTR, CH2048B, mb0);
            issue4(smem_u32(stage[1]), b0 + 1024, GSTR, CH2048B, mb1);
        }
        {
            const float4* gh4 = (const float4*)g_h[pin];
            float4* s4 = (float4*)vsm;
#pragma unroll
            for (int k = 0; k < 4; ++k) s4[tid + k * 128] = gh4[tid + k * 128];
        }
        __syncthreads();

        for (int g = 0; g < ng; ++g) {
            const int j = n0 + HALF * g;
            const float* nb = whh + (size_t)(n0 + HALF * (g + 1)) * I_DIM;

            mbar_wait(mb0, g & 1);
            float acc = chunk_dot<8>(stage[0] + w * 256, (const float4*)vsm, lane);
            __syncthreads();
            if (tid == 0 && g + 1 < ng) {
                fence_async();
                issue4(smem_u32(stage[0]), nb, GSTR, CH2048B, mb0);
            }

            mbar_wait(mb1, g & 1);
            acc += chunk_dot<8>(stage[1] + w * 256, (const float4*)vsm + 256, lane);
            acc = warp_sum(acc);
            if (lane == 0) dots[w] = acc;
            __syncthreads();
            if (tid == 0) {
                if (g + 1 < ng) {
                    fence_async();
                    issue4(smem_u32(stage[1]), nb + 1024, GSTR, CH2048B, mb1);
                }
                const float* z = g_z + zoff;
                float gi = z[j]             + dots[0];
                float gf = z[I_DIM + j]     + dots[1];
                float gg = z[2 * I_DIM + j] + dots[2];
                float go = z[3 * I_DIM + j] + dots[3];
                float c  = sigmoidf_(gf) * g_c[pin][j] + sigmoidf_(gi) * tanhf(gg);
                float h  = sigmoidf_(go) * tanhf(c);
                g_c[pout][j] = c;
                g_h[pout][j] = h;
            }
        }
    } else {
        // ---------------- z role ----------------
        const int n0  = blockIdx.x - HALF;
        const int lim = (mode == 0) ? 2048 : 256;
        if (n0 >= lim) return;
        const int ng = (lim - n0 + HALF - 1) / HALF;
        const int K        = (mode == 0) ? I_DIM : DM;
        const int halfF    = K / 2;                   // 1024 or 896
        const uint32_t chB = (mode == 0) ? CH2048B : CH1792B;

        auto rowbase = [&](int s) -> int {
            if (mode == 0) return s * 4;
            int rl = s * 4;
            return (rl >> 8) * I_DIM + DM + (rl & 255);
        };

        if (tid == 0) {
            const float* b0 = wz + (size_t)rowbase(n0) * K;
            issue4(smem_u32(stage[0]), b0,         K, chB, mb0);
            issue4(smem_u32(stage[1]), b0 + halfF, K, chB, mb1);
        }
        for (int k = tid; k < DM; k += 128) vsm[k] = xvec[k];
        if (mode == 0)
            for (int k = tid; k < BBDIM; k += 128) vsm[DM + k] = yvec[k];
        __syncthreads();

        for (int g = 0; g < ng; ++g) {
            const int r0 = rowbase(n0 + HALF * g);
            const float* nb = (g + 1 < ng)
                ? wz + (size_t)rowbase(n0 + HALF * (g + 1)) * K : nullptr;
            const int cf4 = (mode == 0) ? 256 : 224;  // chunk float4 per row

            mbar_wait(mb0, g & 1);
            float acc = (mode == 0)
                ? chunk_dot<8>(stage[0] + w * 256, (const float4*)vsm, lane)
                : chunk_dot<7>((const float4*)((const char*)stage[0] + w * CH1792B),
                               (const float4*)vsm, lane);
            __syncthreads();
            if (tid == 0 && g + 1 < ng) {
                fence_async();
                issue4(smem_u32(stage[0]), nb, K, chB, mb0);
            }

            mbar_wait(mb1, g & 1);
            acc += (mode == 0)
                ? chunk_dot<8>(stage[1] + w * 256, (const float4*)vsm + 256, lane)
                : chunk_dot<7>((const float4*)((const char*)stage[1] + w * CH1792B),
                               (const float4*)vsm + 224, lane);
            acc = warp_sum(acc);
            if (lane == 0) {
                const int r = r0 + w;
                g_z[zout + r] = acc + bih[r] + bhh[r];
            }
            __syncthreads();
            if (tid == 0 && g + 1 < ng) {
                fence_async();
                issue4(smem_u32(stage[1]), nb + halfF, K, chB, mb1);
            }
            (void)cf4;
        }
    }
}

// ---------------------------------------------------------------------------
// Final step: j in [1792,2048). 256 blocks, 1 j each (8.4 MB total).
// ---------------------------------------------------------------------------
__global__ void __launch_bounds__(128) final_pipe(
    const float* __restrict__ whhF, int pin, float* __restrict__ out)
{
    __shared__ float4 stage[2][1024];
    __shared__ float  vsm[I_DIM];
    __shared__ float  dots[4];
    __shared__ __align__(8) unsigned long long mbar[2];

    const int tid = threadIdx.x, w = tid >> 5, lane = tid & 31;
    const uint32_t mb0 = smem_u32(&mbar[0]), mb1 = smem_u32(&mbar[1]);

    if (tid == 0) { mbar_init(mb0, 1); mbar_init(mb1, 1); fence_async(); }
    __syncthreads();

    const int j = DM + blockIdx.x;
    const size_t GSTR = (size_t)I_DIM * I_DIM;
    if (tid == 0) {
        const float* b0 = whhF + (size_t)j * I_DIM;
        issue4(smem_u32(stage[0]), b0,        GSTR, CH2048B, mb0);
        issue4(smem_u32(stage[1]), b0 + 1024, GSTR, CH2048B, mb1);
    }
    {
        const float4* gh4 = (const float4*)g_h[pin];
        float4* s4 = (float4*)vsm;
#pragma unroll
        for (int k = 0; k < 4; ++k) s4[tid + k * 128] = gh4[tid + k * 128];
    }
    __syncthreads();

    mbar_wait(mb0, 0);
    float acc = chunk_dot<8>(stage[0] + w * 256, (const float4*)vsm, lane);
    mbar_wait(mb1, 0);
    acc += chunk_dot<8>(stage[1] + w * 256, (const float4*)vsm + 256, lane);
    acc = warp_sum(acc);
    if (lane == 0) dots[w] = acc;
    __syncthreads();

    if (tid == 0) {
        const float* z = g_z + 5 * G_DIM;
        float gi = z[j]             + dots[0];
        float gf = z[I_DIM + j]     + dots[1];
        float gg = z[2 * I_DIM + j] + dots[2];
        float go = z[3 * I_DIM + j] + dots[3];
        float c  = sigmoidf_(gf) * g_c[pin][j] + sigmoidf_(gi) * tanhf(gg);
        float h  = sigmoidf_(go) * tanhf(c);
        out[j - DM] = h;
    }
}

// ---------------------------------------------------------------------------
extern "C" void kernel_launch(void* const* d_in, const int* in_sizes, int n_in,
                              void* d_out, int out_size)
{
    const float* x    = (const float*)d_in[0];
    const float* y    = (const float*)d_in[1];
    const float* Wih5 = (const float*)d_in[2];
    const float* Whh5 = (const float*)d_in[3];
    const float* bih5 = (const float*)d_in[4];
    const float* bhh5 = (const float*)d_in[5];
    const float* WihF = (const float*)d_in[6];
    const float* WhhF = (const float*)d_in[7];
    const float* bihF = (const float*)d_in[8];
    const float* bhhF = (const float*)d_in[9];
    float* out = (float*)d_out;

    (void)in_sizes; (void)n_in; (void)out_size;

    const size_t WSTEP = (size_t)G_DIM * I_DIM;

    // K0: z[0], z[1] (134 MB)
    k0_pipe<<<NBF, 128>>>(x, y, Wih5, bih5, bhh5);

    // step 0 (h0=c0=0: skips Whh5[0], 67 MB)
    step0_kernel<<<(I_DIM + 255) / 256, 256>>>();

    // S1..S3: rec t + z(t+1) (134 MB each)
    int pin = 0;
    for (int t = 1; t <= 3; ++t) {
        fused_pipe<<<NBF, 128>>>(
            Whh5 + (size_t)t * WSTEP, t * G_DIM, pin, 1 - pin,
            Wih5 + (size_t)(t + 1) * WSTEP,
            x + (t + 1) * DM, y + (t + 1) * BBDIM,
            bih5 + (size_t)(t + 1) * G_DIM, bhh5 + (size_t)(t + 1) * G_DIM,
            (t + 1) * G_DIM, /*mode=*/0);
        pin = 1 - pin;
    }

    // S4: rec 4 + final-cell z slice (67 + 7.3 MB)
    fused_pipe<<<NBF, 128>>>(
        Whh5 + (size_t)4 * WSTEP, 4 * G_DIM, pin, 1 - pin,
        WihF, x + 5 * DM, nullptr,
        bihF, bhhF, 5 * G_DIM, /*mode=*/1);
    pin = 1 - pin;

    // S5: final step, 256 outputs (8.4 MB)
    final_pipe<<<256, 128>>>(WhhF, pin, out);
}